// round 1
// baseline (speedup 1.0000x reference)
#include <cuda_runtime.h>
#include <cstdint>
#include <cstddef>

// Problem constants (fixed by the dataset)
#define N_TOKENS 8192      // B*S = 4*2048
#define HDIM     1024      // H
#define NHEADS   16
#define SLOTS    16
#define SD       32
#define HD       64

// Scratch for action probabilities [token][head][3]
__device__ float g_actions[N_TOKENS * NHEADS * 3];

// ---------------------------------------------------------------------------
// Kernel 1: actions = softmax_3( (hidden @ Wa + ba) / 8 )
// Tiled GEMM: 64 tokens x 48 cols per block, 256 threads, reg tile 4x3.
// ---------------------------------------------------------------------------
__global__ __launch_bounds__(256) void k_actions(
    const float* __restrict__ hidden,
    const float* __restrict__ Wa,
    const float* __restrict__ ba)
{
    __shared__ float sA[64][65];   // padded: conflict-free column reads
    __shared__ float sW[64][48];

    const int tid = threadIdx.x;
    const int tx  = tid & 15;      // head / col-group (3 cols each)
    const int ty  = tid >> 4;      // token group (4 tokens each)
    const int tok0 = blockIdx.x * 64;

    float acc[4][3];
#pragma unroll
    for (int i = 0; i < 4; i++)
#pragma unroll
        for (int j = 0; j < 3; j++) acc[i][j] = 0.f;

    for (int k0 = 0; k0 < HDIM; k0 += 64) {
        // load A tile 64x64 (coalesced per row)
#pragma unroll
        for (int i = tid; i < 64 * 64; i += 256) {
            int tt = i >> 6, kk = i & 63;
            sA[tt][kk] = hidden[(size_t)(tok0 + tt) * HDIM + k0 + kk];
        }
        // load W tile 64x48 (contiguous slab of Wa)
#pragma unroll
        for (int i = tid; i < 64 * 48; i += 256) {
            (&sW[0][0])[i] = Wa[(size_t)k0 * 48 + i];
        }
        __syncthreads();

#pragma unroll 8
        for (int kk = 0; kk < 64; kk++) {
            float w0 = sW[kk][tx * 3 + 0];
            float w1 = sW[kk][tx * 3 + 1];
            float w2 = sW[kk][tx * 3 + 2];
#pragma unroll
            for (int i = 0; i < 4; i++) {
                float a = sA[ty * 4 + i][kk];
                acc[i][0] = fmaf(a, w0, acc[i][0]);
                acc[i][1] = fmaf(a, w1, acc[i][1]);
                acc[i][2] = fmaf(a, w2, acc[i][2]);
            }
        }
        __syncthreads();
    }

    const float b0 = ba[tx * 3 + 0];
    const float b1 = ba[tx * 3 + 1];
    const float b2 = ba[tx * 3 + 2];
    const float scale = 0.125f;  // 1/sqrt(64)

#pragma unroll
    for (int i = 0; i < 4; i++) {
        float l0 = (acc[i][0] + b0) * scale;
        float l1 = (acc[i][1] + b1) * scale;
        float l2 = (acc[i][2] + b2) * scale;
        float mx = fmaxf(l0, fmaxf(l1, l2));
        float e0 = __expf(l0 - mx);
        float e1 = __expf(l1 - mx);
        float e2 = __expf(l2 - mx);
        float inv = 1.f / (e0 + e1 + e2);
        size_t base = (size_t)(tok0 + ty * 4 + i) * 48 + tx * 3;
        g_actions[base + 0] = e0 * inv;
        g_actions[base + 1] = e1 * inv;
        g_actions[base + 2] = e2 * inv;
    }
}

// ---------------------------------------------------------------------------
// Kernel 2: per-token stack update + gated readout + residual output.
// 1 block per token, 512 threads: warp h = head h, lane = stack-dim.
// ---------------------------------------------------------------------------
__global__ __launch_bounds__(512, 2) void k_stack(
    const float* __restrict__ hidden,
    const float* __restrict__ stack,
    const float* __restrict__ mask,
    const float* __restrict__ Wd,
    const float* __restrict__ bd,
    const float* __restrict__ Wu,
    const float* __restrict__ bu,
    const float* __restrict__ Wg,
    const float* __restrict__ bg,
    const float* __restrict__ res_w,
    float* __restrict__ out,
    float* __restrict__ new_stack,
    float* __restrict__ new_mask)
{
    const int token = blockIdx.x;
    const int tid   = threadIdx.x;
    const int h     = tid >> 5;
    const int lane  = tid & 31;

    __shared__ float sh_hidden[HDIM];                 // 4 KB
    __shared__ float sh_Wg[SD];                       // 128 B
    __shared__ float sh_ns[NHEADS][SLOTS * 33];       // 33 KB, padded transpose
    __shared__ float sh_nm[NHEADS][SLOTS];            // 1 KB
    __shared__ float sh_gate[NHEADS][SLOTS];          // 1 KB
    __shared__ float sh_mem[NHEADS][SD];              // 2 KB

    // block loads
    sh_hidden[tid]       = __ldcs(&hidden[(size_t)token * HDIM + tid]);
    sh_hidden[tid + 512] = __ldcs(&hidden[(size_t)token * HDIM + tid + 512]);
    if (tid < SD) sh_Wg[tid] = Wg[tid];
    __syncthreads();

    // ---- k projection: k[lane] = bd[lane] + sum_d hidden[h*64+d]*Wd[d][lane]
    float kv = bd[lane];
    const float* hh = &sh_hidden[h * HD];
#pragma unroll 16
    for (int d = 0; d < HD; d++)
        kv = fmaf(hh[d], __ldg(&Wd[d * SD + lane]), kv);

    // ---- action probs (broadcast loads)
    const float* act = &g_actions[(size_t)token * 48 + h * 3];
    const float a_push = act[0];
    const float a_pop  = act[1];
    const float a_noop = act[2];

    // ---- load stack row (16 slots, coalesced 128B each, MLP=16, streaming)
    const size_t th = (size_t)(token * NHEADS + h);
    const float* stk = stack + th * (SLOTS * SD) + lane;
    float st[16];
#pragma unroll
    for (int s = 0; s < SLOTS; s++) st[s] = __ldcs(&stk[s * SD]);

    // masks: broadcast loads (uniform address per lane)
    const float* mk = mask + th * SLOTS;
    float m[16];
#pragma unroll
    for (int s = 0; s < SLOTS; s++) m[s] = __ldcs(&mk[s]);

    // ---- streaming stack/mask update; write new_stack to gmem + smem transpose
    float* nsrow = &sh_ns[h][0];
    float* gst   = new_stack + th * (SLOTS * SD) + lane;
    float prevS = kv;     // push source at slot 0 = k
    float prevM = 1.0f;   // push_mask at slot 0 = 1
#pragma unroll
    for (int s = 0; s < SLOTS; s++) {
        float nxtS = (s < SLOTS - 1) ? st[s + 1] : 0.f;
        float ns = fmaf(a_push, prevS, fmaf(a_pop, nxtS, a_noop * st[s]));
        nsrow[s * 33 + lane] = ns;
        __stcs(&gst[s * SD], ns);
        prevS = st[s];

        float nxtM = (s < SLOTS - 1) ? m[s + 1] : 0.f;
        float nm = fmaf(a_push, prevM, fmaf(a_pop, nxtM, a_noop * m[s]));
        if (lane == 0) sh_nm[h][s] = nm;
        prevM = m[s];
    }
    __syncwarp();

    // ---- gate: lanes (mod 16) each own one slot
    {
        const int slot = lane & 15;
        float gs = bg[0];
#pragma unroll
        for (int sd = 0; sd < SD; sd++)
            gs = fmaf(nsrow[slot * 33 + sd], sh_Wg[sd], gs);
        float sc = gs + (1.f - sh_nm[h][slot]) * (-1e9f);
        // softmax over 16 slots within half-warp
        float mx = sc;
#pragma unroll
        for (int o = 8; o >= 1; o >>= 1)
            mx = fmaxf(mx, __shfl_xor_sync(0xffffffffu, mx, o, 16));
        float e = __expf(sc - mx);
        float ssum = e;
#pragma unroll
        for (int o = 8; o >= 1; o >>= 1)
            ssum += __shfl_xor_sync(0xffffffffu, ssum, o, 16);
        if (lane < 16) sh_gate[h][slot] = e / ssum;
    }
    __syncwarp();

    // ---- write new_mask (coalesced 64B)
    if (lane < SLOTS)
        __stcs(&new_mask[th * SLOTS + lane], sh_nm[h][lane]);

    // ---- mem[sd=lane] = sum_slot ns[slot][lane] * gate[slot]
    float mem = 0.f;
#pragma unroll
    for (int s = 0; s < SLOTS; s++)
        mem = fmaf(nsrow[s * 33 + lane], sh_gate[h][s], mem);
    sh_mem[h][lane] = mem;
    __syncwarp();

    // ---- up-projection + residual: each lane does d = lane, lane+32
    const float rw = res_w[0];
#pragma unroll
    for (int r = 0; r < 2; r++) {
        const int d = lane + r * 32;
        float o = bu[d];
#pragma unroll
        for (int sd = 0; sd < SD; sd++)
            o = fmaf(sh_mem[h][sd], __ldg(&Wu[sd * HD + d]), o);
        __stcs(&out[(size_t)token * HDIM + h * HD + d],
               fmaf(o, rw, sh_hidden[h * HD + d]));
    }
}

// ---------------------------------------------------------------------------
extern "C" void kernel_launch(void* const* d_in, const int* in_sizes, int n_in,
                              void* d_out, int out_size)
{
    const float* hidden = (const float*)d_in[0];
    const float* stack  = (const float*)d_in[1];
    const float* mask   = (const float*)d_in[2];
    const float* Wa     = (const float*)d_in[3];
    const float* ba     = (const float*)d_in[4];
    const float* Wd     = (const float*)d_in[5];
    const float* bd     = (const float*)d_in[6];
    const float* Wu     = (const float*)d_in[7];
    const float* bu     = (const float*)d_in[8];
    const float* Wg     = (const float*)d_in[9];
    const float* bg     = (const float*)d_in[10];
    const float* res_w  = (const float*)d_in[11];

    float* out       = (float*)d_out;
    float* new_stack = out + (size_t)N_TOKENS * HDIM;                       // 8,388,608
    float* new_mask  = new_stack + (size_t)N_TOKENS * NHEADS * SLOTS * SD;  // +67,108,864

    (void)in_sizes; (void)n_in; (void)out_size;

    k_actions<<<N_TOKENS / 64, 256>>>(hidden, Wa, ba);
    k_stack<<<N_TOKENS, 512>>>(hidden, stack, mask, Wd, bd, Wu, bu,
                               Wg, bg, res_w, out, new_stack, new_mask);
}

// round 2
// speedup vs baseline: 1.1243x; 1.1243x over previous
#include <cuda_runtime.h>
#include <cstdint>
#include <cstddef>

#define N_TOKENS 8192
#define HDIM     1024
#define NHEADS   16
#define SLOTS    16
#define SD       32
#define HD       64

// Packed action probabilities per (token, head): {a_push, a_pop, a_noop, pad}
__device__ float4 g_act4[N_TOKENS * NHEADS];

// ---------------------------------------------------------------------------
// Kernel 1: actions = softmax_3( (hidden @ Wa + ba) / 8 )
// 16 tokens x 48 cols per block, 128 threads, thread tile 2 tok x 3 col,
// float4-vectorized over k.
// ---------------------------------------------------------------------------
__global__ __launch_bounds__(128) void k_actions(
    const float* __restrict__ hidden,
    const float* __restrict__ Wa,
    const float* __restrict__ ba)
{
    __shared__ float sA[16][68];    // 16 tokens x 64 k (padded, 16B-aligned rows)
    __shared__ float sWT[48][68];   // transposed Wa tile: [col][k]

    const int tid  = threadIdx.x;
    const int tg   = tid >> 4;     // token group 0..7 (2 tokens)
    const int hx   = tid & 15;     // head 0..15 (3 cols)
    const int tok0 = blockIdx.x * 16;

    float acc[2][3];
#pragma unroll
    for (int i = 0; i < 2; i++)
#pragma unroll
        for (int j = 0; j < 3; j++) acc[i][j] = 0.f;

    for (int k0 = 0; k0 < HDIM; k0 += 64) {
        // load A tile (float4, coalesced)
#pragma unroll
        for (int i = tid; i < 16 * 16; i += 128) {
            int r = i >> 4, c = i & 15;
            *(float4*)&sA[r][c * 4] =
                *(const float4*)&hidden[(size_t)(tok0 + r) * HDIM + k0 + c * 4];
        }
        // load + transpose W tile
#pragma unroll
        for (int i = tid; i < 64 * 48; i += 128) {
            int kk = i / 48, col = i % 48;
            sWT[col][kk] = Wa[(size_t)(k0 + kk) * 48 + col];
        }
        __syncthreads();

#pragma unroll
        for (int c4 = 0; c4 < 16; c4++) {
            float4 a0 = *(const float4*)&sA[tg * 2 + 0][c4 * 4];
            float4 a1 = *(const float4*)&sA[tg * 2 + 1][c4 * 4];
            float4 w0 = *(const float4*)&sWT[hx * 3 + 0][c4 * 4];
            float4 w1 = *(const float4*)&sWT[hx * 3 + 1][c4 * 4];
            float4 w2 = *(const float4*)&sWT[hx * 3 + 2][c4 * 4];
            acc[0][0] = fmaf(a0.x,w0.x,fmaf(a0.y,w0.y,fmaf(a0.z,w0.z,fmaf(a0.w,w0.w,acc[0][0]))));
            acc[0][1] = fmaf(a0.x,w1.x,fmaf(a0.y,w1.y,fmaf(a0.z,w1.z,fmaf(a0.w,w1.w,acc[0][1]))));
            acc[0][2] = fmaf(a0.x,w2.x,fmaf(a0.y,w2.y,fmaf(a0.z,w2.z,fmaf(a0.w,w2.w,acc[0][2]))));
            acc[1][0] = fmaf(a1.x,w0.x,fmaf(a1.y,w0.y,fmaf(a1.z,w0.z,fmaf(a1.w,w0.w,acc[1][0]))));
            acc[1][1] = fmaf(a1.x,w1.x,fmaf(a1.y,w1.y,fmaf(a1.z,w1.z,fmaf(a1.w,w1.w,acc[1][1]))));
            acc[1][2] = fmaf(a1.x,w2.x,fmaf(a1.y,w2.y,fmaf(a1.z,w2.z,fmaf(a1.w,w2.w,acc[1][2]))));
        }
        __syncthreads();
    }

    const float b0 = ba[hx * 3 + 0];
    const float b1 = ba[hx * 3 + 1];
    const float b2 = ba[hx * 3 + 2];
    const float scale = 0.125f;  // 1/sqrt(64)

#pragma unroll
    for (int i = 0; i < 2; i++) {
        float l0 = (acc[i][0] + b0) * scale;
        float l1 = (acc[i][1] + b1) * scale;
        float l2 = (acc[i][2] + b2) * scale;
        float mx = fmaxf(l0, fmaxf(l1, l2));
        float e0 = __expf(l0 - mx);
        float e1 = __expf(l1 - mx);
        float e2 = __expf(l2 - mx);
        float inv = 1.f / (e0 + e1 + e2);
        g_act4[(size_t)(tok0 + tg * 2 + i) * NHEADS + hx] =
            make_float4(e0 * inv, e1 * inv, e2 * inv, 0.f);
    }
}

// ---------------------------------------------------------------------------
// Kernel 2: stack update + gated readout + residual.
// 1 block/token, 16 warps = heads, lane = stack-dim. No smem transpose:
// gate scores via linearity of Wg-dot + warp butterfly.
// ---------------------------------------------------------------------------
__global__ __launch_bounds__(512, 2) void k_stack(
    const float* __restrict__ hidden,
    const float* __restrict__ stack,
    const float* __restrict__ mask,
    const float* __restrict__ Wd,
    const float* __restrict__ bd,
    const float* __restrict__ Wu,
    const float* __restrict__ bu,
    const float* __restrict__ Wg,
    const float* __restrict__ bg,
    const float* __restrict__ res_w,
    float* __restrict__ out,
    float* __restrict__ new_stack,
    float* __restrict__ new_mask)
{
    const int token = blockIdx.x;
    const int tid   = threadIdx.x;
    const int h     = tid >> 5;
    const int lane  = tid & 31;

    __shared__ float sh_hidden[HDIM];       // 4 KB
    __shared__ float sWdT[SD][68];          // 8.7 KB : WdT[sd][d]
    __shared__ float sWuT[HD][68];          // 17.4 KB: WuT[d][sd]
    __shared__ float sh_mem[NHEADS][SD];    // 2 KB

    sh_hidden[tid]       = __ldcs(&hidden[(size_t)token * HDIM + tid]);
    sh_hidden[tid + 512] = __ldcs(&hidden[(size_t)token * HDIM + tid + 512]);
#pragma unroll
    for (int i = tid; i < HD * SD; i += 512) {          // Wd[d][sd] -> WdT[sd][d]
        int d = i >> 5, sd = i & 31;
        sWdT[sd][d] = Wd[i];
    }
#pragma unroll
    for (int i = tid; i < SD * HD; i += 512) {          // Wu[sd][d] -> WuT[d][sd]
        int sd = i >> 6, d = i & 63;
        sWuT[d][sd] = Wu[i];
    }
    __syncthreads();

    // ---- k projection: kv[lane] = bd[lane] + hh . WdT[lane][:]
    float kv = __ldg(&bd[lane]);
    const float* hh = &sh_hidden[h * HD];
#pragma unroll
    for (int d4 = 0; d4 < 16; d4++) {
        float4 h4 = *(const float4*)&hh[d4 * 4];                // uniform broadcast
        float4 w4 = *(const float4*)&sWdT[lane][d4 * 4];        // per-lane row
        kv = fmaf(h4.x, w4.x, fmaf(h4.y, w4.y, fmaf(h4.z, w4.z, fmaf(h4.w, w4.w, kv))));
    }

    const size_t th = (size_t)token * NHEADS + h;
    const float4 act = __ldg(&g_act4[th]);
    const float a_push = act.x, a_pop = act.y, a_noop = act.z;
    const float wg = __ldg(&Wg[lane]);

    // ---- load stack (16 coalesced 128B loads, streaming)
    const float* stk = stack + th * (SLOTS * SD) + lane;
    float st[16];
#pragma unroll
    for (int s = 0; s < SLOTS; s++) st[s] = __ldcs(&stk[s * SD]);

    // ---- q[s] = Wg . stack[s]  (butterfly reduce, result in all lanes)
    float q[16];
#pragma unroll
    for (int s = 0; s < SLOTS; s++) q[s] = st[s] * wg;
#pragma unroll
    for (int off = 16; off >= 1; off >>= 1) {
#pragma unroll
        for (int s = 0; s < SLOTS; s++)
            q[s] += __shfl_xor_sync(0xffffffffu, q[s], off);
    }
    float qk = kv * wg;
#pragma unroll
    for (int off = 16; off >= 1; off >>= 1)
        qk += __shfl_xor_sync(0xffffffffu, qk, off);

    // ---- gate scores (uniform across warp), mask recurrence fused.
    // sc[s] stored into q[s-1] (q[s-1] dead after use); sc0 separate.
    const float bgv = __ldg(&bg[0]);
    const float* mk = mask + th * SLOTS;
    float mprev = 1.f;
    float mcur  = __ldcs(&mk[0]);
    float nm_mine = 0.f;     // per-lane new_mask value (lane == slot)
    float mx = -3.4e38f;
    float sc0 = 0.f;
#pragma unroll
    for (int s = 0; s < SLOTS; s++) {
        float mnext = (s < SLOTS - 1) ? __ldcs(&mk[s + 1]) : 0.f;
        float nm = fmaf(a_push, mprev, fmaf(a_pop, mnext, a_noop * mcur));
        float qprev = (s == 0) ? qk : q[s - 1];
        float qnext = (s < SLOTS - 1) ? q[s + 1] : 0.f;
        float gs = fmaf(a_push, qprev, fmaf(a_pop, qnext, a_noop * q[s])) + bgv;
        float scv = gs + (1.f - nm) * (-1e9f);
        if (s == 0) sc0 = scv; else q[s - 1] = scv;
        mx = fmaxf(mx, scv);
        nm_mine = (lane == s) ? nm : nm_mine;
        mprev = mcur; mcur = mnext;
    }
    // softmax (all values uniform in registers)
    sc0 = __expf(sc0 - mx);
    float ssum = sc0;
#pragma unroll
    for (int s = 1; s < SLOTS; s++) {
        q[s - 1] = __expf(q[s - 1] - mx);
        ssum += q[s - 1];
    }
    const float ginv = 1.f / ssum;

    if (lane < SLOTS)
        __stcs(&new_mask[th * SLOTS + lane], nm_mine);

    // ---- stack recurrence + streamed store + gated accumulation
    float* gst = new_stack + th * (SLOTS * SD) + lane;
    float mem = 0.f;
    float prevS = kv;
#pragma unroll
    for (int s = 0; s < SLOTS; s++) {
        float nxt = (s < SLOTS - 1) ? st[s + 1] : 0.f;
        float ns = fmaf(a_push, prevS, fmaf(a_pop, nxt, a_noop * st[s]));
        prevS = st[s];
        __stcs(&gst[s * SD], ns);
        float gate = (s == 0) ? sc0 : q[s - 1];
        mem = fmaf(gate, ns, mem);
    }
    sh_mem[h][lane] = mem * ginv;
    __syncwarp();

    // ---- up-projection + residual
    float o0 = __ldg(&bu[lane]);
    float o1 = __ldg(&bu[lane + 32]);
#pragma unroll
    for (int sd4 = 0; sd4 < 8; sd4++) {
        float4 m4 = *(const float4*)&sh_mem[h][sd4 * 4];        // broadcast
        float4 wA = *(const float4*)&sWuT[lane][sd4 * 4];
        float4 wB = *(const float4*)&sWuT[lane + 32][sd4 * 4];
        o0 = fmaf(m4.x, wA.x, fmaf(m4.y, wA.y, fmaf(m4.z, wA.z, fmaf(m4.w, wA.w, o0))));
        o1 = fmaf(m4.x, wB.x, fmaf(m4.y, wB.y, fmaf(m4.z, wB.z, fmaf(m4.w, wB.w, o1))));
    }
    const float rw = __ldg(&res_w[0]);
    __stcs(&out[(size_t)token * HDIM + h * HD + lane],
           fmaf(o0, rw, sh_hidden[h * HD + lane]));
    __stcs(&out[(size_t)token * HDIM + h * HD + lane + 32],
           fmaf(o1, rw, sh_hidden[h * HD + lane + 32]));
}

// ---------------------------------------------------------------------------
extern "C" void kernel_launch(void* const* d_in, const int* in_sizes, int n_in,
                              void* d_out, int out_size)
{
    const float* hidden = (const float*)d_in[0];
    const float* stack  = (const float*)d_in[1];
    const float* mask   = (const float*)d_in[2];
    const float* Wa     = (const float*)d_in[3];
    const float* ba     = (const float*)d_in[4];
    const float* Wd     = (const float*)d_in[5];
    const float* bd     = (const float*)d_in[6];
    const float* Wu     = (const float*)d_in[7];
    const float* bu     = (const float*)d_in[8];
    const float* Wg     = (const float*)d_in[9];
    const float* bg     = (const float*)d_in[10];
    const float* res_w  = (const float*)d_in[11];

    float* out       = (float*)d_out;
    float* new_stack = out + (size_t)N_TOKENS * HDIM;
    float* new_mask  = new_stack + (size_t)N_TOKENS * NHEADS * SLOTS * SD;

    (void)in_sizes; (void)n_in; (void)out_size;

    k_actions<<<N_TOKENS / 16, 128>>>(hidden, Wa, ba);
    k_stack<<<N_TOKENS, 512>>>(hidden, stack, mask, Wd, bd, Wu, bu,
                               Wg, bg, res_w, out, new_stack, new_mask);
}

// round 3
// speedup vs baseline: 1.2389x; 1.1019x over previous
#include <cuda_runtime.h>
#include <cstdint>
#include <cstddef>

#define N_TOKENS 8192
#define HDIM     1024
#define NHEADS   16
#define SLOTS    16
#define SD       32
#define HD       64
#define FULLMASK 0xffffffffu

__device__ float4 g_act4[N_TOKENS * NHEADS];
__device__ float  g_WaT[48 * HDIM];          // WaT[col][k]

// ---------------------- float4 helpers ----------------------
__device__ __forceinline__ float4 f4zero() { return make_float4(0.f, 0.f, 0.f, 0.f); }
__device__ __forceinline__ float4 f4fma(float a, float4 b, float4 c) {
    return make_float4(fmaf(a, b.x, c.x), fmaf(a, b.y, c.y),
                       fmaf(a, b.z, c.z), fmaf(a, b.w, c.w));
}
__device__ __forceinline__ float4 f4add(float4 a, float4 b) {
    return make_float4(a.x + b.x, a.y + b.y, a.z + b.z, a.w + b.w);
}
__device__ __forceinline__ float dot4(float4 a, float4 b) {
    return fmaf(a.x, b.x, fmaf(a.y, b.y, fmaf(a.z, b.z, a.w * b.w)));
}
__device__ __forceinline__ float4 f4shflxor(float4 v, int m) {
    return make_float4(__shfl_xor_sync(FULLMASK, v.x, m),
                       __shfl_xor_sync(FULLMASK, v.y, m),
                       __shfl_xor_sync(FULLMASK, v.z, m),
                       __shfl_xor_sync(FULLMASK, v.w, m));
}

// ---------------------------------------------------------------------------
// Kernel 0: transpose Wa [1024][48] -> g_WaT [48][1024]
// ---------------------------------------------------------------------------
__global__ __launch_bounds__(256) void k_waT(const float* __restrict__ Wa)
{
    const int col = blockIdx.x;
    for (int k = threadIdx.x; k < HDIM; k += 256)
        g_WaT[col * HDIM + k] = Wa[(size_t)k * 48 + col];
}

// ---------------------------------------------------------------------------
// Kernel 1: actions = softmax_3( (hidden @ Wa + ba) / 8 )
// 32 tokens/block, 256 threads, thread tile 2 tok x 3 col, fp32 FMA.
// ---------------------------------------------------------------------------
__global__ __launch_bounds__(256) void k_actions(
    const float* __restrict__ hidden,
    const float* __restrict__ ba)
{
    __shared__ float sA[32][68];
    __shared__ float sWT[48][68];

    const int tid  = threadIdx.x;
    const int tg   = tid >> 4;     // 0..15 (2 tokens each)
    const int hx   = tid & 15;     // head (3 cols)
    const int tok0 = blockIdx.x * 32;
    const float4* hid4 = (const float4*)hidden;
    const float4* waT4 = (const float4*)g_WaT;

    float acc[2][3];
#pragma unroll
    for (int i = 0; i < 2; i++)
#pragma unroll
        for (int j = 0; j < 3; j++) acc[i][j] = 0.f;

    for (int k0 = 0; k0 < HDIM; k0 += 64) {
#pragma unroll
        for (int idx = tid; idx < 512; idx += 256) {   // A tile 32x16 f4
            int r = idx >> 4, c4 = idx & 15;
            *(float4*)&sA[r][c4 * 4] = hid4[(size_t)(tok0 + r) * 256 + (k0 >> 2) + c4];
        }
#pragma unroll
        for (int idx = tid; idx < 768; idx += 256) {   // W tile 48x16 f4
            int r = idx >> 4, c4 = idx & 15;
            *(float4*)&sWT[r][c4 * 4] = waT4[(size_t)r * 256 + (k0 >> 2) + c4];
        }
        __syncthreads();

#pragma unroll
        for (int c4 = 0; c4 < 16; c4++) {
            float4 a0 = *(const float4*)&sA[tg * 2 + 0][c4 * 4];
            float4 a1 = *(const float4*)&sA[tg * 2 + 1][c4 * 4];
            float4 w0 = *(const float4*)&sWT[hx * 3 + 0][c4 * 4];
            float4 w1 = *(const float4*)&sWT[hx * 3 + 1][c4 * 4];
            float4 w2 = *(const float4*)&sWT[hx * 3 + 2][c4 * 4];
            acc[0][0] = fmaf(a0.x,w0.x,fmaf(a0.y,w0.y,fmaf(a0.z,w0.z,fmaf(a0.w,w0.w,acc[0][0]))));
            acc[0][1] = fmaf(a0.x,w1.x,fmaf(a0.y,w1.y,fmaf(a0.z,w1.z,fmaf(a0.w,w1.w,acc[0][1]))));
            acc[0][2] = fmaf(a0.x,w2.x,fmaf(a0.y,w2.y,fmaf(a0.z,w2.z,fmaf(a0.w,w2.w,acc[0][2]))));
            acc[1][0] = fmaf(a1.x,w0.x,fmaf(a1.y,w0.y,fmaf(a1.z,w0.z,fmaf(a1.w,w0.w,acc[1][0]))));
            acc[1][1] = fmaf(a1.x,w1.x,fmaf(a1.y,w1.y,fmaf(a1.z,w1.z,fmaf(a1.w,w1.w,acc[1][1]))));
            acc[1][2] = fmaf(a1.x,w2.x,fmaf(a1.y,w2.y,fmaf(a1.z,w2.z,fmaf(a1.w,w2.w,acc[1][2]))));
        }
        __syncthreads();
    }

    const float b0 = ba[hx * 3 + 0];
    const float b1 = ba[hx * 3 + 1];
    const float b2 = ba[hx * 3 + 2];

#pragma unroll
    for (int i = 0; i < 2; i++) {
        float l0 = (acc[i][0] + b0) * 0.125f;
        float l1 = (acc[i][1] + b1) * 0.125f;
        float l2 = (acc[i][2] + b2) * 0.125f;
        float mx = fmaxf(l0, fmaxf(l1, l2));
        float e0 = __expf(l0 - mx);
        float e1 = __expf(l1 - mx);
        float e2 = __expf(l2 - mx);
        float inv = 1.f / (e0 + e1 + e2);
        g_act4[(size_t)(tok0 + tg * 2 + i) * NHEADS + hx] =
            make_float4(e0 * inv, e1 * inv, e2 * inv, 0.f);
    }
}

// ---------------------------------------------------------------------------
// Kernel 2: stack update + gated readout + residual.
// Block = 8 heads of one token (256 thr), warp = head.
// Lane layout: g = lane>>3 (slot%4-group), c = lane&7 (sd4). reg i: slot=i*4+g.
// ---------------------------------------------------------------------------
__global__ __launch_bounds__(256, 3) void k_stack(
    const float* __restrict__ hidden,
    const float* __restrict__ stack,
    const float* __restrict__ mask,
    const float* __restrict__ Wd,
    const float* __restrict__ bd,
    const float* __restrict__ Wu,
    const float* __restrict__ bu,
    const float* __restrict__ Wg,
    const float* __restrict__ bg,
    const float* __restrict__ res_w,
    float* __restrict__ out,
    float* __restrict__ new_stack,
    float* __restrict__ new_mask)
{
    const int token  = blockIdx.x >> 1;
    const int hhalf  = blockIdx.x & 1;
    const int tid    = threadIdx.x;
    const int wl     = tid >> 5;            // warp in block: 0..7
    const int h      = hhalf * 8 + wl;
    const int lane   = tid & 31;
    const int g      = lane >> 3;           // 0..3
    const int c      = lane & 7;            // 0..7

    __shared__ float4 sHid[128];            // this half's 512 hidden floats
    __shared__ float4 sWd[512];             // raw Wd [d][sd]: f4 idx d*8+c
    __shared__ float4 sWu[512];             // raw Wu [sd][d]: f4 idx sd*16+d4
    __shared__ float4 sMem[8][8];

    // fills
    if (tid < 128)
        sHid[tid] = __ldcs(&((const float4*)hidden)[(size_t)token * 256 + hhalf * 128 + tid]);
    sWd[tid]       = ((const float4*)Wd)[tid];
    sWd[tid + 256] = ((const float4*)Wd)[tid + 256];
    sWu[tid]       = ((const float4*)Wu)[tid];
    sWu[tid + 256] = ((const float4*)Wu)[tid + 256];
    __syncthreads();

    const size_t th = (size_t)token * NHEADS + h;
    const float4* stk4 = (const float4*)stack + th * 128;

    // ---- stack loads + neighbor loads (slot = i*4+g, sd4 = c, f4 idx = i*32+lane)
    float4 st[4], nx[4], pv[4];
#pragma unroll
    for (int i = 0; i < 4; i++) st[i] = __ldcs(&stk4[i * 32 + lane]);
#pragma unroll
    for (int i = 0; i < 4; i++) {
        const int slot = i * 4 + g;
        nx[i] = (slot < 15) ? __ldcs(&stk4[i * 32 + lane + 8]) : f4zero();
        pv[i] = (slot > 0)  ? __ldcs(&stk4[i * 32 + lane - 8]) : f4zero();
    }

    // ---- masks (all within one 64B line)
    const float* mk = mask + th * SLOTS;
    float m[4], mn[4], mp[4];
#pragma unroll
    for (int i = 0; i < 4; i++) {
        const int slot = i * 4 + g;
        m[i]  = __ldcs(&mk[slot]);
        mn[i] = (slot < 15) ? __ldcs(&mk[slot + 1]) : 0.f;
        mp[i] = (slot > 0)  ? __ldcs(&mk[slot - 1]) : 1.f;
    }

    // ---- kv4: sd range [4c,4c+4); partial over d in [g*16, g*16+16)
    float4 kp = f4zero();
#pragma unroll
    for (int t4 = 0; t4 < 4; t4++) {
        float4 h4 = sHid[wl * 16 + g * 4 + t4];
        const int dbase = g * 16 + t4 * 4;
        kp = f4fma(h4.x, sWd[(dbase + 0) * 8 + c], kp);
        kp = f4fma(h4.y, sWd[(dbase + 1) * 8 + c], kp);
        kp = f4fma(h4.z, sWd[(dbase + 2) * 8 + c], kp);
        kp = f4fma(h4.w, sWd[(dbase + 3) * 8 + c], kp);
    }
    kp = f4add(kp, f4shflxor(kp, 8));
    kp = f4add(kp, f4shflxor(kp, 16));
    float4 kv4 = f4add(kp, __ldg(&((const float4*)bd)[c]));

    // ---- actions, Wg
    const float4 act = g_act4[th];
    const float a_push = act.x, a_pop = act.y, a_noop = act.z;
    const float4 wg4 = __ldg(&((const float4*)Wg)[c]);

    // ---- q[s] = Wg . stack[s]  (reduce over c: xor 1,2,4)
    float q[4];
#pragma unroll
    for (int i = 0; i < 4; i++) {
        q[i] = dot4(st[i], wg4);
        q[i] += __shfl_xor_sync(FULLMASK, q[i], 1);
        q[i] += __shfl_xor_sync(FULLMASK, q[i], 2);
        q[i] += __shfl_xor_sync(FULLMASK, q[i], 4);
    }
    float qk = dot4(kv4, wg4);
    qk += __shfl_xor_sync(FULLMASK, qk, 1);
    qk += __shfl_xor_sync(FULLMASK, qk, 2);
    qk += __shfl_xor_sync(FULLMASK, qk, 4);

    // ---- q neighbors via send-rotation
    float qn[4], qp[4];
#pragma unroll
    for (int i = 0; i < 4; i++) {
        float sn = (g == 0) ? ((i < 3) ? q[i + 1] : 0.f) : q[i];
        qn[i] = __shfl_sync(FULLMASK, sn, (lane + 8) & 31);
        float sp = (g == 3) ? ((i > 0) ? q[i - 1] : 0.f) : q[i];
        qp[i] = __shfl_sync(FULLMASK, sp, (lane + 24) & 31);
    }
    if (g == 0) qp[0] = qk;   // slot 0: prev = k

    // ---- new_mask + gate scores
    const float bgv = __ldg(&bg[0]);
    float nm[4], e[4];
    float mx = -3.4e38f;
#pragma unroll
    for (int i = 0; i < 4; i++) {
        nm[i] = fmaf(a_push, mp[i], fmaf(a_pop, mn[i], a_noop * m[i]));
        float sc = fmaf(a_push, qp[i], fmaf(a_pop, qn[i], a_noop * q[i])) + bgv;
        sc += (1.f - nm[i]) * (-1e9f);
        e[i] = sc;
        mx = fmaxf(mx, sc);
    }
    mx = fmaxf(mx, __shfl_xor_sync(FULLMASK, mx, 8));
    mx = fmaxf(mx, __shfl_xor_sync(FULLMASK, mx, 16));
    float ssum = 0.f;
#pragma unroll
    for (int i = 0; i < 4; i++) { e[i] = __expf(e[i] - mx); ssum += e[i]; }
    ssum += __shfl_xor_sync(FULLMASK, ssum, 8);
    ssum += __shfl_xor_sync(FULLMASK, ssum, 16);
    const float ginv = 1.f / ssum;

    if (c == 0) {
#pragma unroll
        for (int i = 0; i < 4; i++)
            __stcs(&new_mask[th * SLOTS + i * 4 + g], nm[i]);
    }

    // ---- new_stack + gated accumulation
    if (g == 0) pv[0] = kv4;   // slot 0 push source = k
    float4* nst4 = (float4*)new_stack + th * 128;
    float4 acc = f4zero();
#pragma unroll
    for (int i = 0; i < 4; i++) {
        float4 ns;
        ns.x = fmaf(a_push, pv[i].x, fmaf(a_pop, nx[i].x, a_noop * st[i].x));
        ns.y = fmaf(a_push, pv[i].y, fmaf(a_pop, nx[i].y, a_noop * st[i].y));
        ns.z = fmaf(a_push, pv[i].z, fmaf(a_pop, nx[i].z, a_noop * st[i].z));
        ns.w = fmaf(a_push, pv[i].w, fmaf(a_pop, nx[i].w, a_noop * st[i].w));
        __stcs(&nst4[i * 32 + lane], ns);
        acc = f4fma(e[i] * ginv, ns, acc);
    }
    // reduce over g (slots): xor 8,16 -> mem[4c..4c+3]
    acc = f4add(acc, f4shflxor(acc, 8));
    acc = f4add(acc, f4shflxor(acc, 16));

    if (g == 0) sMem[wl][c] = acc;
    __syncwarp();

    // ---- up-projection: lane -> d4 = lane&15, half = lane>>4
    const int d4 = lane & 15;
    const int half = lane >> 4;
    const float* memf = (const float*)&sMem[wl][0];
    float4 p = f4zero();
#pragma unroll
    for (int t = 0; t < 16; t++) {
        float mv = memf[half * 16 + t];
        p = f4fma(mv, sWu[(half * 16 + t) * 16 + d4], p);
    }
    p = f4add(p, f4shflxor(p, 16));   // combine sd halves

    const float4 bu4 = __ldg(&((const float4*)bu)[d4]);
    const float4 hid = sHid[wl * 16 + d4];
    const float rw = __ldg(&res_w[0]);
    float4 o;
    o.x = fmaf(p.x + bu4.x, rw, hid.x);
    o.y = fmaf(p.y + bu4.y, rw, hid.y);
    o.z = fmaf(p.z + bu4.z, rw, hid.z);
    o.w = fmaf(p.w + bu4.w, rw, hid.w);
    if (lane < 16)
        __stcs(&((float4*)out)[(size_t)token * 256 + h * 16 + d4], o);
}

// ---------------------------------------------------------------------------
extern "C" void kernel_launch(void* const* d_in, const int* in_sizes, int n_in,
                              void* d_out, int out_size)
{
    const float* hidden = (const float*)d_in[0];
    const float* stack  = (const float*)d_in[1];
    const float* mask   = (const float*)d_in[2];
    const float* Wa     = (const float*)d_in[3];
    const float* ba     = (const float*)d_in[4];
    const float* Wd     = (const float*)d_in[5];
    const float* bd     = (const float*)d_in[6];
    const float* Wu     = (const float*)d_in[7];
    const float* bu     = (const float*)d_in[8];
    const float* Wg     = (const float*)d_in[9];
    const float* bg     = (const float*)d_in[10];
    const float* res_w  = (const float*)d_in[11];

    float* out       = (float*)d_out;
    float* new_stack = out + (size_t)N_TOKENS * HDIM;
    float* new_mask  = new_stack + (size_t)N_TOKENS * NHEADS * SLOTS * SD;

    (void)in_sizes; (void)n_in; (void)out_size;

    k_waT<<<48, 256>>>(Wa);
    k_actions<<<N_TOKENS / 32, 256>>>(hidden, ba);
    k_stack<<<N_TOKENS * 2, 256>>>(hidden, stack, mask, Wd, bd, Wu, bu,
                                   Wg, bg, res_w, out, new_stack, new_mask);
}